// round 17
// baseline (speedup 1.0000x reference)
#include <cuda_runtime.h>
#include <cuda_fp16.h>
#include <math.h>
#include <stdint.h>

#define HID   128
#define NODEF 256
#define NBINS 22
#define ETILE 64
#define TW    256
#define WTH_P 136            // table row pitch in halves (272B)
#define HPIT  272            // bytes per h row (256 data + 16 pad); 68 words = 4 mod 32

// ---- smem byte offsets (total 52688 -> 2 CTAs/SM) ----
#define OFF_H1   0           // 64*272 = 17408 (fp16 h1)
#define OFF_H2   17408       // 17408 (fp16 h2)
#define OFF_WTH  34816       // half[45][136] = 12240 (row 44 = zeros)
#define OFF_SB2  47056
#define OFF_SB3  47568
#define OFF_SG   48080
#define OFF_SBT  48592
#define OFF_MSK  49104       // float[2][64]
#define OFF_BIN1 49616       // int[2][64]
#define OFF_BIN2 50128       // int[2][64]
#define OFF_RSUM 50640       // float[4][64]
#define OFF_RSQ  51664       // float[4][64]
#define SMEM_BYTES 52688

__device__ uint4 g_Ah[512 * HID / 8];    // fp16 A rows
__device__ uint4 g_Bh[512 * HID / 8];    // fp16 B rows
__device__ uint4 g_Rh[1023 * HID / 8];   // fp16 R rows
__device__ uint4 g_w2[2048], g_w3[2048]; // W2/W3 fp16 fragment tiles (B-operand layout)

// ---- helpers ----
__device__ __forceinline__ uint32_t pkh(float a, float b) {  // lo half = a
    __half2 h = __floats2half2_rn(a, b);
    return *reinterpret_cast<uint32_t*>(&h);
}
__device__ __forceinline__ uint32_t hadd2(uint32_t a, uint32_t b) {
    uint32_t d;
    asm("add.f16x2 %0, %1, %2;" : "=r"(d) : "r"(a), "r"(b));
    return d;
}
__device__ __forceinline__ uint32_t hmax2z(uint32_t a) {
    uint32_t d;
    asm("max.f16x2 %0, %1, %2;" : "=r"(d) : "r"(a), "r"(0u));
    return d;
}
__device__ __forceinline__ void mma16816(float (&d)[4], const uint4& a, uint32_t b0, uint32_t b1) {
    asm volatile("mma.sync.aligned.m16n8k16.row.col.f32.f16.f16.f32 "
                 "{%0,%1,%2,%3}, {%4,%5,%6,%7}, {%8,%9}, {%0,%1,%2,%3};"
                 : "+f"(d[0]), "+f"(d[1]), "+f"(d[2]), "+f"(d[3])
                 : "r"(a.x), "r"(a.y), "r"(a.z), "r"(a.w), "r"(b0), "r"(b1));
}
__device__ __forceinline__ uint4 ldmat4(uint32_t a) {
    uint4 r;
    asm volatile("ldmatrix.sync.aligned.m8n8.x4.shared.b16 {%0,%1,%2,%3}, [%4];"
                 : "=r"(r.x), "=r"(r.y), "=r"(r.z), "=r"(r.w) : "r"(a));
    return r;
}
__device__ __forceinline__ void stmat2(uint32_t a, uint32_t r0, uint32_t r1) {
    asm volatile("stmatrix.sync.aligned.m8n8.x2.shared.b16 [%0], {%1,%2};"
                 :: "r"(a), "r"(r0), "r"(r1));
}
__device__ __forceinline__ uint32_t smem_u32(const void* p) {
    uint32_t a;
    asm("{ .reg .u64 t; cvta.to.shared.u64 t, %1; cvt.u32.u64 %0, t; }" : "=r"(a) : "l"(p));
    return a;
}

// ---- merged precompute: [0,N) A/B rows; [N,3N-1) R rows; [3N-1, +64) W frags ----
__global__ void k_pre2(const float* __restrict__ nf, const float* __restrict__ Wn,
                       const float* __restrict__ bn, const float* __restrict__ W1,
                       const float* __restrict__ b1, const float* __restrict__ flow,
                       const float* __restrict__ Wrp, const float* __restrict__ brp,
                       const float* __restrict__ W2, const float* __restrict__ W3,
                       int N) {
    const int c = threadIdx.x;
    if ((int)blockIdx.x < N) {
        __shared__ float row[NODEF];
        __shared__ float n2e[HID];
        const int i = blockIdx.x;
        row[c] = nf[i * NODEF + c];
        row[c + 128] = nf[i * NODEF + 128 + c];
        __syncthreads();
        float s0 = bn[c], s1 = 0.0f;
#pragma unroll 4
        for (int k = 0; k < NODEF; k += 2) {
            s0 += row[k] * Wn[k * HID + c];
            s1 += row[k + 1] * Wn[(k + 1) * HID + c];
        }
        n2e[c] = s0 + s1;
        __syncthreads();
        const float fi = flow[i];
        float a0 = b1[c] + fi * W1[428 * HID + c], a1 = 0.0f;
        float b0 = fi * W1[429 * HID + c], bb1 = 0.0f;
#pragma unroll 4
        for (int k = 0; k < HID; k += 2) {
            const float v0 = n2e[k], v1 = n2e[k + 1];
            a0 += v0 * W1[k * HID + c];
            a1 += v1 * W1[(k + 1) * HID + c];
            b0 += v0 * W1[(128 + k) * HID + c];
            bb1 += v1 * W1[(128 + k + 1) * HID + c];
        }
        ((__half*)g_Ah)[i * HID + c] = __float2half_rn(a0 + a1);
        ((__half*)g_Bh)[i * HID + c] = __float2half_rn(b0 + bb1);
    } else if ((int)blockIdx.x < 3 * N - 1) {
        __shared__ float emb[HID];
        __shared__ float rp[HID];
        const int bi = blockIdx.x - N;
        const float d = (float)(bi - (N - 1));
        if (c < 64) {
            float den = (float)pow(2056.0, (double)c * (1.0 / 64.0));
            float ang = (d * 3.14159274101257324f) / den;
            emb[c] = (float)sin((double)ang);
            emb[c + 64] = (float)cos((double)ang);
        }
        __syncthreads();
        float s0 = brp[c], s1 = 0.0f;
#pragma unroll 4
        for (int k = 0; k < HID; k += 2) {
            s0 += emb[k] * Wrp[k * HID + c];
            s1 += emb[k + 1] * Wrp[(k + 1) * HID + c];
        }
        rp[c] = s0 + s1;
        __syncthreads();
        float r0 = 0.0f, r1 = 0.0f;
#pragma unroll 4
        for (int k = 0; k < HID; k += 2) {
            r0 += rp[k] * W1[(256 + k) * HID + c];
            r1 += rp[k + 1] * W1[(256 + k + 1) * HID + c];
        }
        ((__half*)g_Rh)[bi * HID + c] = __float2half_rn(r0 + r1);
    } else {
        const int idx = (blockIdx.x - (3 * N - 1)) * 128 + c;
        const int n = idx >> 6, k = (idx & 63) * 2;
        const int ntg = n >> 3, gg = n & 7;
        const int t = (k >> 1) & 3, ks = k >> 4, r = (k >> 3) & 1;
        const int w = ((((ks * 8 + (ntg >> 1)) * 32 + 4 * gg + t) << 2) + ((ntg & 1) << 1) + r);
        ((uint32_t*)g_w2)[w] = pkh(W2[k * HID + n], W2[(k + 1) * HID + n]);
        ((uint32_t*)g_w3)[w] = pkh(W3[k * HID + n], W3[(k + 1) * HID + n]);
    }
}

__device__ __forceinline__ int calc_bin(const float* __restrict__ p, int i, int j) {
    const float dx = __ldg(&p[3 * i + 0]) - __ldg(&p[3 * j + 0]);
    const float dy = __ldg(&p[3 * i + 1]) - __ldg(&p[3 * j + 1]);
    const float dz = __ldg(&p[3 * i + 2]) - __ldg(&p[3 * j + 2]);
    const float d = sqrtf((dx * dx + dy * dy) + dz * dz);
    const float step = (20.0f - 0.001f) / 21.0f;
    int bin = -1;
#pragma unroll
    for (int k = 0; k < NBINS; k++) {
        const float lo = 0.001f + (float)k * step;
        const float hi = (k == NBINS - 1) ? 1e8f : (0.001f + (float)(k + 1) * step);
        if (d > lo && d < hi) bin = k;
    }
    return bin;
}

// bins + mask for one tile (call with tid < ETILE)
__device__ __forceinline__ void do_bins(int t, int tpr, int N,
                                        const float* __restrict__ trans,
                                        const float* __restrict__ sctrans,
                                        const float* __restrict__ emask,
                                        int* sb1, int* sb2, float* smk, int tid) {
    const int i = t / tpr;
    const int j = (t - i * tpr) * ETILE + tid;
    const int q1 = calc_bin(trans, i, j);
    const int q2 = calc_bin(sctrans, i, j);
    sb1[tid] = (q1 < 0 ? 44 : q1) * WTH_P;
    sb2[tid] = (q2 < 0 ? 44 : 22 + q2) * WTH_P;
    smk[tid] = emask[i * N + j];
}

// h1 = relu(A + B + R + T1 + T2), all packed fp16, edge-major store into H1
__device__ __forceinline__ void assemble_h1(char* smc, const __half* sWTh,
                                            const int* sb1, const int* sb2,
                                            int t, int tpr, int N, int wid, int lane) {
    const int i = t / tpr;
    const int jb = (t - i * tpr) * ETILE;
    const int e = 8 * wid + (lane & 7);
    const int sub = lane >> 3;
    const int j = jb + e;
    const __half* aph = (const __half*)g_Ah + i * HID;
    const __half* bph = (const __half*)g_Bh + j * HID;
    const __half* rph = (const __half*)g_Rh + (size_t)(i - j + N - 1) * HID;
    const __half* t1p = sWTh + sb1[e];
    const __half* t2p = sWTh + sb2[e];
#pragma unroll
    for (int cg = 0; cg < 4; cg++) {
        const int c0 = sub * 32 + cg * 8;
        const uint4 a  = __ldg((const uint4*)(aph + c0));
        const uint4 b  = __ldg((const uint4*)(bph + c0));
        const uint4 r  = __ldg((const uint4*)(rph + c0));
        const uint4 t1 = *(const uint4*)(t1p + c0);
        const uint4 t2 = *(const uint4*)(t2p + c0);
        uint4 o;
        o.x = hmax2z(hadd2(hadd2(a.x, b.x), hadd2(hadd2(t1.x, t2.x), r.x)));
        o.y = hmax2z(hadd2(hadd2(a.y, b.y), hadd2(hadd2(t1.y, t2.y), r.y)));
        o.z = hmax2z(hadd2(hadd2(a.z, b.z), hadd2(hadd2(t1.z, t2.z), r.z)));
        o.w = hmax2z(hadd2(hadd2(a.w, b.w), hadd2(hadd2(t1.w, t2.w), r.w)));
        *(uint4*)(smc + OFF_H1 + e * HPIT + c0 * 2) = o;
    }
}

// one layer: warp tile 32 edges x 32 channels; A via ldmatrix (fp16), B via __ldg
__device__ __forceinline__ void gemm_mma(uint32_t hbase, const uint4* __restrict__ wf,
                                         int wm, int wn, int lane, uint32_t lmoff,
                                         float (&acc)[2][4][4]) {
#pragma unroll
    for (int m = 0; m < 2; m++)
#pragma unroll
        for (int nt = 0; nt < 4; nt++)
#pragma unroll
            for (int q = 0; q < 4; q++) acc[m][nt][q] = 0.0f;
    const uint32_t a0b = hbase + (uint32_t)(wm * 32 * HPIT) + lmoff;
#pragma unroll 2
    for (int ks = 0; ks < 8; ks++) {
        const uint32_t ar = a0b + ks * 32;
        const uint4 a0 = ldmat4(ar);
        const uint4 a1 = ldmat4(ar + 16 * HPIT);
#pragma unroll
        for (int pr = 0; pr < 2; pr++) {
            const int prg = wn * 2 + pr;
            const uint4 b = __ldg(&wf[(ks * 8 + prg) * 32 + lane]);
            mma16816(acc[0][2 * pr + 0], a0, b.x, b.y);
            mma16816(acc[1][2 * pr + 0], a1, b.x, b.y);
            mma16816(acc[0][2 * pr + 1], a0, b.z, b.w);
            mma16816(acc[1][2 * pr + 1], a1, b.z, b.w);
        }
    }
}

// ---- main persistent kernel: 256 threads, 2 CTAs/SM, software-pipelined tiles ----
__global__ void __launch_bounds__(TW, 2) k_main(
    const float* __restrict__ trans, const float* __restrict__ sctrans,
    const float* __restrict__ emask, const float* __restrict__ W1,
    const float* __restrict__ b2, const float* __restrict__ b3,
    const float* __restrict__ lng, const float* __restrict__ lnb,
    float* __restrict__ out, int N) {
    extern __shared__ char smc[];
    __half* sWTh = (__half*)(smc + OFF_WTH);
    float* rsum = (float*)(smc + OFF_RSUM);
    float* rsq  = (float*)(smc + OFF_RSQ);

    const int tid = threadIdx.x, lane = tid & 31, wid = tid >> 5;
    const int wm = wid & 1, wn = wid >> 1;   // 2x4 warp grid: 32e x 32c tiles over 64x128
    const int gq = lane >> 2, tq = lane & 3;
    const uint32_t smb = smem_u32(smc);
    const uint32_t h1b = smb + OFF_H1;
    const uint32_t h2b = smb + OFF_H2;
    const uint32_t lmoff = (uint32_t)(((lane & 7) + 8 * ((lane >> 3) & 1)) * HPIT + (lane >> 4) * 16);
    const uint32_t smoff = (uint32_t)(((lane & 7) + 8 * ((lane >> 3) & 1)) * HPIT);

    for (int idx = tid; idx < 45 * HID; idx += TW) {
        const int q = idx >> 7, c = idx & 127;
        sWTh[q * WTH_P + c] = __float2half_rn((q < 44) ? W1[(384 + q) * HID + c] : 0.0f);
    }
    if (tid < HID) {
        ((float*)(smc + OFF_SB2))[tid] = b2[tid];
        ((float*)(smc + OFF_SB3))[tid] = b3[tid];
        ((float*)(smc + OFF_SG))[tid]  = lng[tid];
        ((float*)(smc + OFF_SBT))[tid] = lnb[tid];
    }
    __syncthreads();

    const int tpr = N / ETILE, ntiles = N * tpr;
    const int stride = gridDim.x;
    int t = blockIdx.x;
    int p = 0;

    // prologue: bins + h1 for first tile
    if (t < ntiles) {
        if (tid < ETILE)
            do_bins(t, tpr, N, trans, sctrans, emask,
                    (int*)(smc + OFF_BIN1), (int*)(smc + OFF_BIN2),
                    (float*)(smc + OFF_MSK), tid);
        __syncthreads();
        assemble_h1(smc, sWTh, (int*)(smc + OFF_BIN1), (int*)(smc + OFF_BIN2),
                    t, tpr, N, wid, lane);
        __syncthreads();
    }

    for (; t < ntiles; t += stride, p ^= 1) {
        const int i = t / tpr;
        const int jb = (t - i * tpr) * ETILE;
        const int tn = t + stride;
        const int pn = p ^ 1;

        float acc[2][4][4];

        // ---- layer 2 GEMM (reads H1) + epilogue (bias+relu -> H2) + bins(t+1) ----
        gemm_mma(h1b, g_w2, wm, wn, lane, lmoff, acc);
#pragma unroll
        for (int m = 0; m < 2; m++) {
            const uint32_t rowb = h2b + (uint32_t)((2 * wm + m) * 16 * HPIT) + smoff;
#pragma unroll
            for (int nt = 0; nt < 4; nt++) {
                const int ntg = wn * 4 + nt;
                const int col = ntg * 8 + 2 * tq;
                const float2 bb = *(const float2*)(smc + OFF_SB2 + col * 4);
                const float v0 = fmaxf(acc[m][nt][0] + bb.x, 0.0f);
                const float v1 = fmaxf(acc[m][nt][1] + bb.y, 0.0f);
                const float v2 = fmaxf(acc[m][nt][2] + bb.x, 0.0f);
                const float v3 = fmaxf(acc[m][nt][3] + bb.y, 0.0f);
                stmat2(rowb + (uint32_t)(ntg * 16), pkh(v0, v1), pkh(v2, v3));
            }
        }
        if (tn < ntiles && tid < ETILE)
            do_bins(tn, tpr, N, trans, sctrans, emask,
                    (int*)(smc + OFF_BIN1) + pn * 64, (int*)(smc + OFF_BIN2) + pn * 64,
                    (float*)(smc + OFF_MSK) + pn * 64, tid);
        __syncthreads();   // (a): H2 ready, bins(t+1) ready, H1 fully consumed

        // ---- phase-0 of NEXT tile (overlaps with gemm3 across warps) ----
        if (tn < ntiles)
            assemble_h1(smc, sWTh, (int*)(smc + OFF_BIN1) + pn * 64,
                        (int*)(smc + OFF_BIN2) + pn * 64, tn, tpr, N, wid, lane);

        // ---- layer 3 GEMM (reads H2) ----
        gemm_mma(h2b, g_w3, wm, wn, lane, lmoff, acc);

        // ---- bias + LayerNorm partials ----
        float s[2][2] = {{0, 0}, {0, 0}}, q[2][2] = {{0, 0}, {0, 0}};
#pragma unroll
        for (int m = 0; m < 2; m++)
#pragma unroll
            for (int nt = 0; nt < 4; nt++) {
                const int col = (wn * 4 + nt) * 8 + 2 * tq;
                const float2 bb = *(const float2*)(smc + OFF_SB3 + col * 4);
                acc[m][nt][0] += bb.x;
                acc[m][nt][1] += bb.y;
                acc[m][nt][2] += bb.x;
                acc[m][nt][3] += bb.y;
                s[m][0] += acc[m][nt][0] + acc[m][nt][1];
                s[m][1] += acc[m][nt][2] + acc[m][nt][3];
                q[m][0] += acc[m][nt][0] * acc[m][nt][0] + acc[m][nt][1] * acc[m][nt][1];
                q[m][1] += acc[m][nt][2] * acc[m][nt][2] + acc[m][nt][3] * acc[m][nt][3];
            }
#pragma unroll
        for (int m = 0; m < 2; m++)
#pragma unroll
            for (int h = 0; h < 2; h++) {
                s[m][h] += __shfl_xor_sync(0xffffffffu, s[m][h], 1);
                s[m][h] += __shfl_xor_sync(0xffffffffu, s[m][h], 2);
                q[m][h] += __shfl_xor_sync(0xffffffffu, q[m][h], 1);
                q[m][h] += __shfl_xor_sync(0xffffffffu, q[m][h], 2);
            }
        if (tq == 0) {
#pragma unroll
            for (int m = 0; m < 2; m++)
#pragma unroll
                for (int h = 0; h < 2; h++) {
                    const int row = (2 * wm + m) * 16 + gq + 8 * h;
                    rsum[wn * 64 + row] = s[m][h];
                    rsq[wn * 64 + row] = q[m][h];
                }
        }
        __syncthreads();   // (b): rsum/rsq ready; H1(t+1) stores complete

        // ---- LayerNorm finalize + mask + store ----
        const float* smk = (const float*)(smc + OFF_MSK) + p * 64;
#pragma unroll
        for (int m = 0; m < 2; m++)
#pragma unroll
            for (int h = 0; h < 2; h++) {
                const int row = (2 * wm + m) * 16 + gq + 8 * h;
                const float S = (rsum[row] + rsum[64 + row]) + (rsum[128 + row] + rsum[192 + row]);
                const float Q = (rsq[row] + rsq[64 + row]) + (rsq[128 + row] + rsq[192 + row]);
                const float mu = S * (1.0f / 128.0f);
                const float var = Q * (1.0f / 128.0f) - mu * mu;
                const float rstd = rsqrtf(var + 1e-5f);
                const float msk = smk[row];
                float* op = &out[((size_t)(i * N + jb + row)) * HID];
#pragma unroll
                for (int nt = 0; nt < 4; nt++) {
                    const int col = (wn * 4 + nt) * 8 + 2 * tq;
                    const float2 gg = *(const float2*)(smc + OFF_SG + col * 4);
                    const float2 bt = *(const float2*)(smc + OFF_SBT + col * 4);
                    const float a = acc[m][nt][2 * h + 0];
                    const float b = acc[m][nt][2 * h + 1];
                    float2 o;
                    o.x = ((a - mu) * rstd * gg.x + bt.x) * msk;
                    o.y = ((b - mu) * rstd * gg.y + bt.y) * msk;
                    *(float2*)(op + col) = o;
                }
            }
        // no trailing sync needed: rsum/bins writes next iteration occur after (a)
    }
}

// ---- launch ----
extern "C" void kernel_launch(void* const* d_in, const int* in_sizes, int n_in,
                              void* d_out, int out_size) {
    const float* nf    = (const float*)d_in[0];
    const float* trans = (const float*)d_in[1];
    const float* sct   = (const float*)d_in[2];
    const float* emask = (const float*)d_in[3];
    const float* flow  = (const float*)d_in[4];
    const float* W_n2e = (const float*)d_in[5];
    const float* b_n2e = (const float*)d_in[6];
    const float* W_rp  = (const float*)d_in[7];
    const float* b_rp  = (const float*)d_in[8];
    const float* W1    = (const float*)d_in[9];
    const float* b1    = (const float*)d_in[10];
    const float* W2    = (const float*)d_in[11];
    const float* b2    = (const float*)d_in[12];
    const float* W3    = (const float*)d_in[13];
    const float* b3    = (const float*)d_in[14];
    const float* lng   = (const float*)d_in[15];
    const float* lnb   = (const float*)d_in[16];
    float* out = (float*)d_out;

    const int N = in_sizes[4];

    k_pre2<<<3 * N - 1 + 64, 128>>>(nf, W_n2e, b_n2e, W1, b1, flow, W_rp, b_rp, W2, W3, N);

    cudaFuncSetAttribute((const void*)k_main,
                         cudaFuncAttributeMaxDynamicSharedMemorySize, SMEM_BYTES);
    k_main<<<304, TW, SMEM_BYTES>>>(trans, sct, emask, W1, b2, b3,
                                    lng, lnb, out, N);
}